// round 7
// baseline (speedup 1.0000x reference)
#include <cuda_runtime.h>

#define BATCH 4096

// Block partition (256-thread blocks, warp-owned work, ~32KB per warp).
#define NB3 512                  // L3: warp = 1 row  (8 iters x 8 float4)
#define NB2 128                  // L2: warp = 4 rows (2 iters x 8 per row)
#define NB1 64                   // L1: warp = 8 rows (2 rows/pass, 8 loads)
#define NB0 16                   // L0: warp = 32 rows (4 rows/pass, segmented)
#define NB_CE (NB3 + NB2 + NB1 + NB0)          // 720
#define NBD 16                   // dep: 256 samples/block
#define NB_TOTAL (NB_CE + NBD)                 // 736

__device__ float g_part[NB_CE];  // per-block nll sums
__device__ float g_dep[NBD];     // per-block combined invalid counts
__device__ int   g_done;         // zero-init; self-resets each replay

__device__ __forceinline__ float vec_expsum(float4 v) {
    return __expf(v.x) + __expf(v.y) + __expf(v.z) + __expf(v.w);
}

__device__ __forceinline__ float warp_sum(float s) {
    #pragma unroll
    for (int off = 16; off; off >>= 1)
        s += __shfl_xor_sync(0xffffffffu, s, off);
    return s;
}

__global__ void __launch_bounds__(256, 4)
fused_kernel(const float* __restrict__ o0, const float* __restrict__ o1,
             const float* __restrict__ o2, const float* __restrict__ o3,
             const int* __restrict__ targets,
             const int* __restrict__ p0, const int* __restrict__ p1,
             const int* __restrict__ p2, const int* __restrict__ p3,
             const int* __restrict__ v01, const int* __restrict__ v12,
             const int* __restrict__ v23,
             float* __restrict__ out) {
    const int bid = blockIdx.x;
    const int tid = threadIdx.x;
    const int wid = tid >> 5;
    const int lid = tid & 31;

    __shared__ float sws[8];
    __shared__ bool  is_last;

    float wres = 0.0f;   // this warp's contribution (lane0 meaningful at write)

    if (bid < NB3) {
        // ---- L3: warp owns one 8192-float row; 8 iters of 8 batched float4.
        const int row = bid * 8 + wid;
        const float* rowp = o3 + (size_t)row * 8192u;
        const float4* p = (const float4*)rowp;
        float s0 = 0.0f, s1 = 0.0f, s2 = 0.0f, s3 = 0.0f;
        #pragma unroll
        for (int it = 0; it < 8; it++) {
            float4 v[8];
            #pragma unroll
            for (int k = 0; k < 8; k++) v[k] = __ldcs(p + it * 256 + k * 32 + lid);
            s0 += vec_expsum(v[0]) + vec_expsum(v[4]);
            s1 += vec_expsum(v[1]) + vec_expsum(v[5]);
            s2 += vec_expsum(v[2]) + vec_expsum(v[6]);
            s3 += vec_expsum(v[3]) + vec_expsum(v[7]);
        }
        float s = warp_sum((s0 + s1) + (s2 + s3));
        if (lid == 0) wres = __logf(s) - rowp[targets[row * 4 + 3]];
    } else if (bid < NB3 + NB2) {
        // ---- L2: warp owns 4 rows of 2048 floats; per row 2 iters of 8.
        const int rbase = (bid - NB3) * 32 + wid * 4;
        float acc = 0.0f;
        #pragma unroll
        for (int j = 0; j < 4; j++) {
            const int row = rbase + j;
            const float* rowp = o2 + (size_t)row * 2048u;
            const float4* p = (const float4*)rowp;
            float s0 = 0.0f, s1 = 0.0f, s2 = 0.0f, s3 = 0.0f;
            #pragma unroll
            for (int it = 0; it < 2; it++) {
                float4 v[8];
                #pragma unroll
                for (int k = 0; k < 8; k++) v[k] = __ldcs(p + it * 256 + k * 32 + lid);
                s0 += vec_expsum(v[0]) + vec_expsum(v[4]);
                s1 += vec_expsum(v[1]) + vec_expsum(v[5]);
                s2 += vec_expsum(v[2]) + vec_expsum(v[6]);
                s3 += vec_expsum(v[3]) + vec_expsum(v[7]);
            }
            float s = warp_sum((s0 + s1) + (s2 + s3));
            if (lid == 0) acc += __logf(s) - rowp[targets[row * 4 + 2]];
        }
        wres = acc;
    } else if (bid < NB3 + NB2 + NB1) {
        // ---- L1: warp owns 8 rows of 512 floats; 2 rows per pass (8 loads).
        const int rbase = (bid - NB3 - NB2) * 64 + wid * 8;
        float acc = 0.0f;
        #pragma unroll
        for (int j = 0; j < 4; j++) {
            const int rA = rbase + 2 * j;
            const int rB = rA + 1;
            const float* pA = o1 + (size_t)rA * 512u;
            const float* pB = o1 + (size_t)rB * 512u;
            const float4* qA = (const float4*)pA;
            const float4* qB = (const float4*)pB;
            float4 vA[4], vB[4];
            #pragma unroll
            for (int k = 0; k < 4; k++) { vA[k] = __ldcs(qA + k * 32 + lid);
                                          vB[k] = __ldcs(qB + k * 32 + lid); }
            float sA = (vec_expsum(vA[0]) + vec_expsum(vA[1])) +
                       (vec_expsum(vA[2]) + vec_expsum(vA[3]));
            float sB = (vec_expsum(vB[0]) + vec_expsum(vB[1])) +
                       (vec_expsum(vB[2]) + vec_expsum(vB[3]));
            sA = warp_sum(sA);
            sB = warp_sum(sB);
            if (lid == 0)
                acc += (__logf(sA) - pA[targets[rA * 4 + 1]]) +
                       (__logf(sB) - pB[targets[rB * 4 + 1]]);
        }
        wres = acc;
    } else if (bid < NB_CE) {
        // ---- L0: warp owns 32 rows of 128 floats; 4 rows/pass, 8-lane segments.
        const int rbase = (bid - NB3 - NB2 - NB1) * 256 + wid * 32;
        const int seg = lid >> 3;      // which of 4 rows this lane serves
        const int sl  = lid & 7;       // lane within segment
        float acc = 0.0f;
        #pragma unroll
        for (int it = 0; it < 8; it++) {
            const int row = rbase + it * 4 + seg;
            const float* rowp = o0 + (size_t)row * 128u;
            const float4* p = (const float4*)rowp;
            float4 v[4];
            #pragma unroll
            for (int k = 0; k < 4; k++) v[k] = __ldcs(p + sl + 8 * k);
            float s = (vec_expsum(v[0]) + vec_expsum(v[1])) +
                      (vec_expsum(v[2]) + vec_expsum(v[3]));
            // segmented sum over the 8 lanes of this row
            #pragma unroll
            for (int off = 4; off; off >>= 1)
                s += __shfl_xor_sync(0xffffffffu, s, off);
            if (sl == 0) acc += __logf(s) - rowp[targets[row * 4 + 0]];
        }
        wres = warp_sum(acc);   // leaders hold partials, others 0
    } else {
        // ---- Dep: 256 samples/block; combined invalid count (shared /B factor).
        const int i = (bid - NB_CE) * 256 + tid;
        const int a = p0[i], b = p1[i], c = p2[i], e = p3[i];
        float cnt = 0.0f;
        cnt += (v01[a * 512  + b] == 0) ? 1.0f : 0.0f;
        cnt += (v12[b * 2048 + c] == 0) ? 1.0f : 0.0f;
        cnt += (v23[c * 8192 + e] == 0) ? 1.0f : 0.0f;
        wres = warp_sum(cnt);
    }

    // ---- Per-block combine (one sync per ~256KB of work).
    if (lid == 0) sws[wid] = wres;
    __syncthreads();
    if (tid == 0) {
        float acc = 0.0f;
        #pragma unroll
        for (int w = 0; w < 8; w++) acc += sws[w];
        if (bid < NB_CE) g_part[bid] = acc;
        else             g_dep[bid - NB_CE] = acc;
    }

    // ---- Last-block finalize.
    if (tid == 0) {
        __threadfence();
        int ticket = atomicAdd(&g_done, 1);
        is_last = (ticket == NB_TOTAL - 1);
        if (is_last) g_done = 0;
    }
    __syncthreads();

    if (is_last) {
        float ce = 0.0f;
        for (int i = tid; i < NB_CE; i += 256) ce += __ldcg(&g_part[i]);
        ce = warp_sum(ce);
        if (lid == 0) sws[wid] = ce;
        __syncthreads();
        if (tid == 0) {
            float ce_sum = 0.0f;
            #pragma unroll
            for (int w = 0; w < 8; w++) ce_sum += sws[w];

            float depcnt = 0.0f;
            #pragma unroll
            for (int j = 0; j < NBD; j++) depcnt += __ldcg(&g_dep[j]);

            const float E_MINUS_1 = 1.7182818284590452f;
            const float inv_b = 1.0f / (float)BATCH;
            float ce_total  = ce_sum * inv_b;
            float dep_total = E_MINUS_1 * depcnt * inv_b;
            out[0] = 0.5f * ce_total + 0.5f * dep_total;
            out[1] = ce_total;
            out[2] = dep_total;
        }
    }
}

extern "C" void kernel_launch(void* const* d_in, const int* in_sizes, int n_in,
                              void* d_out, int out_size) {
    const float* o0 = (const float*)d_in[0];
    const float* o1 = (const float*)d_in[1];
    const float* o2 = (const float*)d_in[2];
    const float* o3 = (const float*)d_in[3];
    const int* targets = (const int*)d_in[4];
    const int* p0 = (const int*)d_in[5];
    const int* p1 = (const int*)d_in[6];
    const int* p2 = (const int*)d_in[7];
    const int* p3 = (const int*)d_in[8];
    const int* v01 = (const int*)d_in[9];
    const int* v12 = (const int*)d_in[10];
    const int* v23 = (const int*)d_in[11];
    float* out = (float*)d_out;

    fused_kernel<<<NB_TOTAL, 256>>>(o0, o1, o2, o3, targets,
                                    p0, p1, p2, p3, v01, v12, v23, out);
}

// round 8
// speedup vs baseline: 1.0655x; 1.0655x over previous
#include <cuda_runtime.h>
#include <cstdint>

#define BATCH 4096

// ---- chunked work layout: uniform 32KB chunks (8192 floats) ----
#define CHUNK_FLOATS 8192
#define CHUNK_BYTES  32768
#define C3_END 4096              // L3: 1 row/chunk   (4096 chunks)
#define C2_END 5120              // L2: 4 rows/chunk  (1024 chunks)
#define C1_END 5376              // L1: 16 rows/chunk (256 chunks)
#define NCHUNK 5440              // L0: 64 rows/chunk (64 chunks)

#define CE_CTAS 296              // 2 CTAs/SM x 148 SMs
#define NBD 8                    // dep blocks: 512 samples each
#define NB_TOTAL (CE_CTAS + NBD)
#define NSTAGE 3

__device__ float g_part[CE_CTAS];
__device__ float g_dep[NBD];
__device__ int   g_done;         // zero-init; self-resets each replay

__device__ __forceinline__ float vec_expsum(float4 v) {
    return __expf(v.x) + __expf(v.y) + __expf(v.z) + __expf(v.w);
}
__device__ __forceinline__ float warp_sum(float s) {
    #pragma unroll
    for (int off = 16; off; off >>= 1)
        s += __shfl_xor_sync(0xffffffffu, s, off);
    return s;
}
__device__ __forceinline__ uint32_t smem_u32(const void* p) {
    return (uint32_t)__cvta_generic_to_shared(p);
}
__device__ __forceinline__ void mbar_init(uint32_t a) {
    asm volatile("mbarrier.init.shared.b64 [%0], 1;" :: "r"(a) : "memory");
}
__device__ __forceinline__ void mbar_wait(uint32_t a, int parity) {
    asm volatile(
        "{\n\t.reg .pred P;\n\t"
        "W%=:\n\t"
        "mbarrier.try_wait.parity.acquire.cta.shared::cta.b64 P, [%0], %1, 0x989680;\n\t"
        "@P bra D%=;\n\t"
        "bra W%=;\n\t"
        "D%=:\n\t}"
        :: "r"(a), "r"(parity) : "memory");
}
__device__ __forceinline__ void bulk_load(uint32_t dst, const void* src,
                                          uint32_t bytes, uint32_t mbar) {
    asm volatile("mbarrier.arrive.expect_tx.shared.b64 _, [%0], %1;"
                 :: "r"(mbar), "r"(bytes) : "memory");
    asm volatile(
        "cp.async.bulk.shared::cluster.global.mbarrier::complete_tx::bytes "
        "[%0], [%1], %2, [%3];"
        :: "r"(dst), "l"(src), "r"(bytes), "r"(mbar) : "memory");
}

__global__ void __launch_bounds__(256)
fused_kernel(const float* __restrict__ o0, const float* __restrict__ o1,
             const float* __restrict__ o2, const float* __restrict__ o3,
             const int* __restrict__ targets,
             const int* __restrict__ p0, const int* __restrict__ p1,
             const int* __restrict__ p2, const int* __restrict__ p3,
             const int* __restrict__ v01, const int* __restrict__ v12,
             const int* __restrict__ v23,
             float* __restrict__ out) {
    extern __shared__ float stage[];              // NSTAGE * 8192 floats
    __shared__ unsigned long long mbar_s[NSTAGE];
    __shared__ float sws[8];
    __shared__ bool  is_last;

    const int bid = blockIdx.x;
    const int tid = threadIdx.x;
    const int wid = tid >> 5;
    const int lid = tid & 31;

    float acc = 0.0f;

    if (bid < CE_CTAS) {
        // ---------- CE: cp.async.bulk pipelined streaming ----------
        uint32_t mb[NSTAGE];
        uint32_t stg[NSTAGE];
        #pragma unroll
        for (int s = 0; s < NSTAGE; s++) {
            mb[s]  = smem_u32(&mbar_s[s]);
            stg[s] = smem_u32(&stage[s * CHUNK_FLOATS]);
        }
        if (tid == 0) {
            #pragma unroll
            for (int s = 0; s < NSTAGE; s++) mbar_init(mb[s]);
        }
        __syncthreads();

        // source address for global chunk id c
        auto src_of = [&](int c) -> const float* {
            if (c < C3_END) return o3 + (size_t)c * CHUNK_FLOATS;
            if (c < C2_END) return o2 + (size_t)(c - C3_END) * CHUNK_FLOATS;
            if (c < C1_END) return o1 + (size_t)(c - C2_END) * CHUNK_FLOATS;
            return o0 + (size_t)(c - C1_END) * CHUNK_FLOATS;
        };

        if (tid == 0) {
            #pragma unroll
            for (int kp = 0; kp < NSTAGE; kp++) {
                int c = bid + kp * CE_CTAS;
                if (c < NCHUNK) bulk_load(stg[kp], src_of(c), CHUNK_BYTES, mb[kp]);
            }
        }

        for (int k = 0, c = bid; c < NCHUNK; k++, c += CE_CTAS) {
            const int s = k % NSTAGE;
            const int parity = (k / NSTAGE) & 1;
            mbar_wait(mb[s], parity);

            const float*  sf = stage + s * CHUNK_FLOATS;
            const float4* st = ((const float4*)sf);

            if (c < C2_END) {
                // L3/L2: per-warp partial over its 1024-float segment.
                const float4* wp = st + wid * 256;
                float a0 = 0.f, a1 = 0.f, a2 = 0.f, a3 = 0.f;
                #pragma unroll
                for (int kk = 0; kk < 2; kk++) {
                    float4 v0 = wp[(kk * 4 + 0) * 32 + lid];
                    float4 v1 = wp[(kk * 4 + 1) * 32 + lid];
                    float4 v2 = wp[(kk * 4 + 2) * 32 + lid];
                    float4 v3 = wp[(kk * 4 + 3) * 32 + lid];
                    a0 += vec_expsum(v0); a1 += vec_expsum(v1);
                    a2 += vec_expsum(v2); a3 += vec_expsum(v3);
                }
                float sw = warp_sum((a0 + a1) + (a2 + a3));
                if (lid == 0) sws[wid] = sw;
            } else if (c < C1_END) {
                // L1: 16 rows of 512; half-warp per row.
                const int h  = lid >> 4;
                const int sl = lid & 15;
                const float4* wp = st + wid * 256 + h * 128;
                float a0 = 0.f, a1 = 0.f;
                #pragma unroll
                for (int kk = 0; kk < 8; kk += 2) {
                    a0 += vec_expsum(wp[(kk + 0) * 16 + sl]);
                    a1 += vec_expsum(wp[(kk + 1) * 16 + sl]);
                }
                float sv = a0 + a1;
                #pragma unroll
                for (int off = 8; off; off >>= 1)
                    sv += __shfl_xor_sync(0xffffffffu, sv, off);
                if (sl == 0) {
                    const int rl  = wid * 2 + h;
                    const int row = (c - C2_END) * 16 + rl;
                    const int t   = targets[row * 4 + 1];
                    acc += __logf(sv) - sf[rl * 512 + t];
                }
            } else {
                // L0: 64 rows of 128; lane-quad per row.
                const int g = lid >> 2;
                const int q = lid & 3;
                const float4* wp = st + wid * 256 + g * 32;
                float a0 = 0.f, a1 = 0.f;
                #pragma unroll
                for (int kk = 0; kk < 8; kk += 2) {
                    a0 += vec_expsum(wp[(kk + 0) * 4 + q]);
                    a1 += vec_expsum(wp[(kk + 1) * 4 + q]);
                }
                float sv = a0 + a1;
                #pragma unroll
                for (int off = 2; off; off >>= 1)
                    sv += __shfl_xor_sync(0xffffffffu, sv, off);
                if (q == 0) {
                    const int rl  = wid * 8 + g;
                    const int row = (c - C1_END) * 64 + rl;
                    const int t   = targets[row * 4 + 0];
                    acc += __logf(sv) - sf[rl * 128 + t];
                }
            }

            __syncthreads();   // all reads of stage s complete

            if (tid == 0) {
                if (c < C3_END) {
                    float ssum = ((sws[0] + sws[1]) + (sws[2] + sws[3])) +
                                 ((sws[4] + sws[5]) + (sws[6] + sws[7]));
                    const int t = targets[c * 4 + 3];
                    acc += __logf(ssum) - sf[t];
                } else if (c < C2_END) {
                    #pragma unroll
                    for (int j = 0; j < 4; j++) {
                        float ssum = sws[2 * j] + sws[2 * j + 1];
                        const int row = (c - C3_END) * 4 + j;
                        const int t   = targets[row * 4 + 2];
                        acc += __logf(ssum) - sf[j * 2048 + t];
                    }
                }
                // refill this stage with chunk k+NSTAGE
                const int cn = c + NSTAGE * CE_CTAS;
                if (cn < NCHUNK) {
                    asm volatile("fence.proxy.async.shared::cta;" ::: "memory");
                    bulk_load(stg[s], src_of(cn), CHUNK_BYTES, mb[s]);
                }
            }
        }

        // block-combine acc -> g_part[bid]
        float ws = warp_sum(acc);
        __syncthreads();                 // sws safe to reuse
        if (lid == 0) sws[wid] = ws;
        __syncthreads();
        if (tid == 0) {
            float a = 0.0f;
            #pragma unroll
            for (int w = 0; w < 8; w++) a += sws[w];
            g_part[bid] = a;
        }
    } else {
        // ---------- Dep: 512 samples/block; combined invalid count ----------
        const int base = (bid - CE_CTAS) * 512;
        float cnt = 0.0f;
        #pragma unroll
        for (int rep = 0; rep < 2; rep++) {
            const int i = base + rep * 256 + tid;
            const int a = p0[i], b = p1[i], cc = p2[i], e = p3[i];
            cnt += (v01[a * 512   + b ] == 0) ? 1.0f : 0.0f;
            cnt += (v12[b * 2048  + cc] == 0) ? 1.0f : 0.0f;
            cnt += (v23[cc * 8192 + e ] == 0) ? 1.0f : 0.0f;
        }
        cnt = warp_sum(cnt);
        if (lid == 0) sws[wid] = cnt;
        __syncthreads();
        if (tid == 0) {
            float a = 0.0f;
            #pragma unroll
            for (int w = 0; w < 8; w++) a += sws[w];
            g_dep[bid - CE_CTAS] = a;
        }
    }

    // ---------- last-block finalize ----------
    if (tid == 0) {
        __threadfence();
        int ticket = atomicAdd(&g_done, 1);
        is_last = (ticket == NB_TOTAL - 1);
        if (is_last) g_done = 0;
    }
    __syncthreads();

    if (is_last) {
        float ce = 0.0f;
        for (int i = tid; i < CE_CTAS; i += 256) ce += __ldcg(&g_part[i]);
        ce = warp_sum(ce);
        if (lid == 0) sws[wid] = ce;
        __syncthreads();
        if (tid == 0) {
            float ce_sum = 0.0f;
            #pragma unroll
            for (int w = 0; w < 8; w++) ce_sum += sws[w];
            float depcnt = 0.0f;
            #pragma unroll
            for (int j = 0; j < NBD; j++) depcnt += __ldcg(&g_dep[j]);

            const float E_MINUS_1 = 1.7182818284590452f;
            const float inv_b = 1.0f / (float)BATCH;
            float ce_total  = ce_sum * inv_b;
            float dep_total = E_MINUS_1 * depcnt * inv_b;
            out[0] = 0.5f * ce_total + 0.5f * dep_total;
            out[1] = ce_total;
            out[2] = dep_total;
        }
    }
}

extern "C" void kernel_launch(void* const* d_in, const int* in_sizes, int n_in,
                              void* d_out, int out_size) {
    const float* o0 = (const float*)d_in[0];
    const float* o1 = (const float*)d_in[1];
    const float* o2 = (const float*)d_in[2];
    const float* o3 = (const float*)d_in[3];
    const int* targets = (const int*)d_in[4];
    const int* p0 = (const int*)d_in[5];
    const int* p1 = (const int*)d_in[6];
    const int* p2 = (const int*)d_in[7];
    const int* p3 = (const int*)d_in[8];
    const int* v01 = (const int*)d_in[9];
    const int* v12 = (const int*)d_in[10];
    const int* v23 = (const int*)d_in[11];
    float* out = (float*)d_out;

    const size_t smem = NSTAGE * CHUNK_BYTES;   // 98304 B
    cudaFuncSetAttribute(fused_kernel,
                         cudaFuncAttributeMaxDynamicSharedMemorySize, (int)smem);
    fused_kernel<<<NB_TOTAL, 256, smem>>>(o0, o1, o2, o3, targets,
                                          p0, p1, p2, p3, v01, v12, v23, out);
}